// round 1
// baseline (speedup 1.0000x reference)
#include <cuda_runtime.h>

// Problem constants
#define T_TOKENS 16384      // 4 * 4096
#define H_DIM    4096
#define N_EXP    64
#define CAP      320        // int(16384/64 * 1.25)

// Scratch: ordered expert picks, slot-major: g_idx[slot*T + t]
__device__ int g_idx[2 * T_TOKENS];

// ---------------------------------------------------------------------------
// Kernel 1: fp32 GEMM  logits[t][e] = sum_h A[t][h] * W[e][h]
// A: [16384, 4096] row-major, W: [64, 4096] row-major, C: [16384, 64]
// Tile: BM=128, BN=64 (all experts), BK=32. 256 threads, micro-tile 8x4.
// ---------------------------------------------------------------------------
#define BM 128
#define BN 64
#define BK 32
#define TM 8
#define TN 4

__global__ __launch_bounds__(256, 1)
void gemm_kernel(const float* __restrict__ A,
                 const float* __restrict__ W,
                 float* __restrict__ C) {
    __shared__ float As[BK][BM + 4];   // stride 132 floats (16B aligned rows)
    __shared__ float Bs[BK][BN + 4];   // stride 68 floats (16B aligned rows)

    const int tid = threadIdx.x;
    const int tx  = tid & 15;          // N direction: 16 * TN = 64
    const int ty  = tid >> 4;          // M direction: 16 * TM = 128
    const int block_m = blockIdx.x * BM;

    const float* Ab = A + (size_t)block_m * H_DIM;

    float acc[TM][TN];
    #pragma unroll
    for (int i = 0; i < TM; i++)
        #pragma unroll
        for (int j = 0; j < TN; j++) acc[i][j] = 0.0f;

    float4 a_reg[4];   // A tile: 128x32 floats = 1024 float4 / 256 thr = 4 each
    float4 b_reg[2];   // B tile:  64x32 floats =  512 float4 / 256 thr = 2 each

    // ---- load chunk 0 ----
    {
        const int k0 = 0;
        #pragma unroll
        for (int j = 0; j < 4; j++) {
            int f = tid + j * 256, row = f >> 3, c4 = f & 7;
            a_reg[j] = *(const float4*)(Ab + (size_t)row * H_DIM + k0 + c4 * 4);
        }
        #pragma unroll
        for (int j = 0; j < 2; j++) {
            int f = tid + j * 256, row = f >> 3, c4 = f & 7;
            b_reg[j] = *(const float4*)(W + (size_t)row * H_DIM + k0 + c4 * 4);
        }
        #pragma unroll
        for (int j = 0; j < 4; j++) {
            int f = tid + j * 256, row = f >> 3, c4 = f & 7;
            As[c4 * 4 + 0][row] = a_reg[j].x;
            As[c4 * 4 + 1][row] = a_reg[j].y;
            As[c4 * 4 + 2][row] = a_reg[j].z;
            As[c4 * 4 + 3][row] = a_reg[j].w;
        }
        #pragma unroll
        for (int j = 0; j < 2; j++) {
            int f = tid + j * 256, row = f >> 3, c4 = f & 7;
            Bs[c4 * 4 + 0][row] = b_reg[j].x;
            Bs[c4 * 4 + 1][row] = b_reg[j].y;
            Bs[c4 * 4 + 2][row] = b_reg[j].z;
            Bs[c4 * 4 + 3][row] = b_reg[j].w;
        }
    }
    __syncthreads();

    const int NCHUNK = H_DIM / BK;     // 128
    for (int kc = 0; kc < NCHUNK; kc++) {
        // prefetch next chunk into registers (overlaps with compute)
        if (kc + 1 < NCHUNK) {
            const int k0 = (kc + 1) * BK;
            #pragma unroll
            for (int j = 0; j < 4; j++) {
                int f = tid + j * 256, row = f >> 3, c4 = f & 7;
                a_reg[j] = *(const float4*)(Ab + (size_t)row * H_DIM + k0 + c4 * 4);
            }
            #pragma unroll
            for (int j = 0; j < 2; j++) {
                int f = tid + j * 256, row = f >> 3, c4 = f & 7;
                b_reg[j] = *(const float4*)(W + (size_t)row * H_DIM + k0 + c4 * 4);
            }
        }

        // compute on current smem tiles
        #pragma unroll
        for (int k = 0; k < BK; k++) {
            float4 a0 = *(const float4*)&As[k][ty * 8];
            float4 a1 = *(const float4*)&As[k][ty * 8 + 4];
            float4 b  = *(const float4*)&Bs[k][tx * 4];
            float av[TM] = {a0.x, a0.y, a0.z, a0.w, a1.x, a1.y, a1.z, a1.w};
            float bv[TN] = {b.x, b.y, b.z, b.w};
            #pragma unroll
            for (int i = 0; i < TM; i++)
                #pragma unroll
                for (int j = 0; j < TN; j++)
                    acc[i][j] = fmaf(av[i], bv[j], acc[i][j]);
        }
        __syncthreads();

        if (kc + 1 < NCHUNK) {
            #pragma unroll
            for (int j = 0; j < 4; j++) {
                int f = tid + j * 256, row = f >> 3, c4 = f & 7;
                As[c4 * 4 + 0][row] = a_reg[j].x;
                As[c4 * 4 + 1][row] = a_reg[j].y;
                As[c4 * 4 + 2][row] = a_reg[j].z;
                As[c4 * 4 + 3][row] = a_reg[j].w;
            }
            #pragma unroll
            for (int j = 0; j < 2; j++) {
                int f = tid + j * 256, row = f >> 3, c4 = f & 7;
                Bs[c4 * 4 + 0][row] = b_reg[j].x;
                Bs[c4 * 4 + 1][row] = b_reg[j].y;
                Bs[c4 * 4 + 2][row] = b_reg[j].z;
                Bs[c4 * 4 + 3][row] = b_reg[j].w;
            }
            __syncthreads();
        }
    }

    // epilogue: write logits
    #pragma unroll
    for (int i = 0; i < TM; i++) {
        int t = block_m + ty * 8 + i;
        float4 v = make_float4(acc[i][0], acc[i][1], acc[i][2], acc[i][3]);
        *(float4*)(C + (size_t)t * N_EXP + tx * 4) = v;
    }
}

// ---------------------------------------------------------------------------
// Kernel 2: per-token top-2 of logits + renormalized weights.
// Monotonic softmax => top-2 of logits; renorm = sigma(l1 - l2).
// jax.lax.top_k tie-break: ascending index order on equal values.
// ---------------------------------------------------------------------------
__global__ __launch_bounds__(256)
void topk_kernel(const float* __restrict__ logits, float* __restrict__ wflat) {
    int t = blockIdx.x * blockDim.x + threadIdx.x;
    if (t >= T_TOKENS) return;
    const float* row = logits + (size_t)t * N_EXP;

    float m1 = -3.4e38f, m2 = -3.4e38f;
    int i1 = 0, i2 = 0;
    #pragma unroll
    for (int e4 = 0; e4 < N_EXP / 4; e4++) {
        float4 r = *(const float4*)(row + e4 * 4);
        float vv[4] = {r.x, r.y, r.z, r.w};
        #pragma unroll
        for (int q = 0; q < 4; q++) {
            float v = vv[q];
            int e = e4 * 4 + q;
            if (v > m1)       { m2 = m1; i2 = i1; m1 = v; i1 = e; }
            else if (v > m2)  { m2 = v; i2 = e; }
        }
    }
    // renormalized top-2 softmax weights
    float w1 = 1.0f / (1.0f + expf(m2 - m1));
    float w2 = 1.0f - w1;

    wflat[t * 2 + 0] = w1;
    wflat[t * 2 + 1] = w2;
    g_idx[t]            = i1;   // slot 0 (slot-major ordering)
    g_idx[T_TOKENS + t] = i2;   // slot 1
}

// ---------------------------------------------------------------------------
// Kernel 3: greedy capacity assignment. One block per expert.
// Ordered sequence a = slot*T + t (slot-major, matching the reference).
// Block-wide ballot prefix-scan maintains each expert's running queue position.
// ---------------------------------------------------------------------------
__global__ __launch_bounds__(256)
void assign_kernel(const float* __restrict__ wflat,
                   float* __restrict__ out_idx,
                   float* __restrict__ out_w) {
    const int e = blockIdx.x;
    const int tid = threadIdx.x;
    const int lane = tid & 31, wid = tid >> 5;

    // zero this expert's output rows (d_out is poisoned)
    for (int i = tid; i < CAP; i += 256) {
        out_idx[e * CAP + i] = 0.0f;
        out_w[e * CAP + i]   = 0.0f;
    }

    __shared__ int wsum[8];
    __syncthreads();

    const int NT = (2 * T_TOKENS) / 256;   // 128 tiles
    int running = 0;
    int ex = g_idx[tid];                    // prefetch tile 0

    for (int tile = 0; tile < NT; tile++) {
        int ex_next = 0;
        if (tile + 1 < NT) ex_next = g_idx[(tile + 1) * 256 + tid];

        bool flag = (ex == e);
        unsigned bal = __ballot_sync(0xffffffffu, flag);
        if (lane == 0) wsum[wid] = __popc(bal);
        int wprefix = __popc(bal & ((1u << lane) - 1u));
        __syncthreads();

        int excl = 0, total = 0;
        #pragma unroll
        for (int w = 0; w < 8; w++) {
            int s = wsum[w];
            if (w < wid) excl += s;
            total += s;
        }

        if (flag) {
            int pos = running + excl + wprefix;
            if (pos < CAP) {
                int a = tile * 256 + tid;
                int token = a & (T_TOKENS - 1);
                int slot  = a >> 14;
                out_idx[e * CAP + pos] = (float)token;
                out_w[e * CAP + pos]   = wflat[token * 2 + slot];
            }
        }
        running += total;
        __syncthreads();   // before wsum reuse
        ex = ex_next;
    }
}

// ---------------------------------------------------------------------------
// Launcher. Output layout (float32, flattened reference-return order):
//   [0 .. 20480)                         expert_indices (E*CAP, int values as float)
//   [20480 .. 40960)                     expert_weights (E*CAP)
//   [40960 .. 73728)                     w_flat (T*2)
//   [73728 .. 73728+16384*64)            router_logits (T*E)
// ---------------------------------------------------------------------------
extern "C" void kernel_launch(void* const* d_in, const int* in_sizes, int n_in,
                              void* d_out, int out_size) {
    const float* hs;
    const float* wr;
    if (in_sizes[0] == N_EXP * H_DIM) {          // identify by element count
        wr = (const float*)d_in[0];
        hs = (const float*)d_in[1];
    } else {
        hs = (const float*)d_in[0];
        wr = (const float*)d_in[1];
    }

    float* out      = (float*)d_out;
    float* out_idx  = out;                               // E*CAP
    float* out_w    = out + N_EXP * CAP;                 // E*CAP
    float* wflat    = out + 2 * N_EXP * CAP;             // T*2
    float* logits   = out + 2 * N_EXP * CAP + 2 * T_TOKENS;  // T*E

    gemm_kernel<<<T_TOKENS / BM, 256>>>(hs, wr, logits);
    topk_kernel<<<T_TOKENS / 256, 256>>>(logits, wflat);
    assign_kernel<<<N_EXP, 256>>>(wflat, out_idx, out_w);
}

// round 4
// speedup vs baseline: 1.5642x; 1.5642x over previous
#include <cuda_runtime.h>
#include <cuda_bf16.h>
#include <cstdint>

#define T_TOKENS 16384
#define H_DIM    4096
#define N_EXP    64
#define CAP      320

__device__ __align__(16) int g_idx[2 * T_TOKENS];

// ---------------------------------------------------------------------------
// helpers
// ---------------------------------------------------------------------------
__device__ __forceinline__ uint32_t smem_to_u32(const void* p) {
    uint32_t a;
    asm("{ .reg .u64 t; cvta.to.shared.u64 t, %1; cvt.u32.u64 %0, t; }" : "=r"(a) : "l"(p));
    return a;
}

#define LDSM_X4(r0, r1, r2, r3, addr)                                          \
    asm volatile("ldmatrix.sync.aligned.m8n8.x4.shared.b16 {%0,%1,%2,%3}, [%4];" \
                 : "=r"(r0), "=r"(r1), "=r"(r2), "=r"(r3) : "r"(addr))

#define MMA16816(d, a0, a1, a2, a3, b0, b1)                                        \
    asm volatile(                                                                  \
        "mma.sync.aligned.m16n8k16.row.col.f32.bf16.bf16.f32 "                     \
        "{%0,%1,%2,%3}, {%4,%5,%6,%7}, {%8,%9}, {%0,%1,%2,%3};"                    \
        : "+f"((d)[0]), "+f"((d)[1]), "+f"((d)[2]), "+f"((d)[3])                   \
        : "r"(a0), "r"(a1), "r"(a2), "r"(a3), "r"(b0), "r"(b1))

__device__ __forceinline__ void cvt_split4(float4 f, uint32_t& h0, uint32_t& h1,
                                           uint32_t& l0, uint32_t& l1) {
    __nv_bfloat162 a = __floats2bfloat162_rn(f.x, f.y);
    __nv_bfloat162 b = __floats2bfloat162_rn(f.z, f.w);
    float r0 = f.x - __bfloat162float(a.x);
    float r1 = f.y - __bfloat162float(a.y);
    float r2 = f.z - __bfloat162float(b.x);
    float r3 = f.w - __bfloat162float(b.y);
    __nv_bfloat162 c = __floats2bfloat162_rn(r0, r1);
    __nv_bfloat162 d = __floats2bfloat162_rn(r2, r3);
    h0 = *(uint32_t*)&a; h1 = *(uint32_t*)&b;
    l0 = *(uint32_t*)&c; l1 = *(uint32_t*)&d;
}

// ---------------------------------------------------------------------------
// smem layout (bytes). Per buffer: Ahi[128x64 bf16, row stride 144B] = 18432,
// Alo = 18432, Bhi[64x64, stride 144B] = 9216, Blo = 9216 -> 55296; x2 buffers.
// Epilogue C (128 x 64 fp32, row stride 66 floats) reuses buffer 0.
// ---------------------------------------------------------------------------
#define SA_STRIDE 144       // bytes per A/B smem row (64 bf16 + 16B pad)
#define BUF_BYTES 55296
#define OFF_AHI(b) ((b) * BUF_BYTES + 0)
#define OFF_ALO(b) ((b) * BUF_BYTES + 18432)
#define OFF_BHI(b) ((b) * BUF_BYTES + 36864)
#define OFF_BLO(b) ((b) * BUF_BYTES + 46080)
#define SMEM_BYTES (2 * BUF_BYTES)
#define CS 66               // C smem row stride in floats

#define NCHUNK 64           // K chunks of 64

// ---------------------------------------------------------------------------
// Fused GEMM (mma.sync bf16 3-product split) + top-2 epilogue.
// CTA: 128 tokens x 64 experts, K = 4096. 8 warps: 4 along M, 2 along N.
// ---------------------------------------------------------------------------
__global__ __launch_bounds__(256, 1)
void gemm_topk_kernel(const float* __restrict__ A,
                      const float* __restrict__ W,
                      float* __restrict__ logits,
                      float* __restrict__ wflat) {
    extern __shared__ char smem[];
    const uint32_t sb = smem_to_u32(smem);
    const int tid  = threadIdx.x;
    const int wid  = tid >> 5;
    const int lane = tid & 31;
    const int wm   = wid & 3;     // M warp: rows [wm*32, +32)
    const int wn   = wid >> 2;    // N warp: cols [wn*32, +32)
    const int block_m = blockIdx.x * 128;

    // global load coords
    const int a_row  = tid >> 1;     // 0..127
    const int a_half = tid & 1;      // 32-float half of the 64-wide chunk
    const int b_row  = tid >> 2;     // 0..63
    const int b_q    = tid & 3;      // 16-float quarter

    const float* Abase = A + (size_t)(block_m + a_row) * H_DIM + a_half * 32;
    const float* Wbase = W + (size_t)b_row * H_DIM + b_q * 16;

    // ldmatrix base addresses (lane-dependent), before per-buffer/per-k16 offsets
    const uint32_t a_lds = (uint32_t)((wm * 32 + (lane & 15)) * SA_STRIDE + (lane >> 4) * 16);
    const uint32_t b_lds = (uint32_t)((wn * 32 + (lane & 7) + ((lane >> 4) & 1) * 8) * SA_STRIDE +
                                      ((lane >> 3) & 1) * 16);

    float acc[2][4][4];
    #pragma unroll
    for (int i = 0; i < 2; i++)
        #pragma unroll
        for (int j = 0; j < 4; j++)
            #pragma unroll
            for (int q = 0; q < 4; q++) acc[i][j][q] = 0.0f;

    float4 fA[8], fB[4];

    // ---- prologue: load + convert + store chunk 0 into buffer 0 ----
    #pragma unroll
    for (int i = 0; i < 8; i++) fA[i] = ((const float4*)(Abase))[i];
    #pragma unroll
    for (int i = 0; i < 4; i++) fB[i] = ((const float4*)(Wbase))[i];
    {
        char* ah = smem + OFF_AHI(0) + a_row * SA_STRIDE + a_half * 64;
        char* al = smem + OFF_ALO(0) + a_row * SA_STRIDE + a_half * 64;
        #pragma unroll
        for (int i = 0; i < 4; i++) {
            uint32_t h[4], l[4];
            cvt_split4(fA[i * 2 + 0], h[0], h[1], l[0], l[1]);
            cvt_split4(fA[i * 2 + 1], h[2], h[3], l[2], l[3]);
            *(uint4*)(ah + i * 16) = *(uint4*)h;
            *(uint4*)(al + i * 16) = *(uint4*)l;
        }
        char* bh = smem + OFF_BHI(0) + b_row * SA_STRIDE + b_q * 32;
        char* bl = smem + OFF_BLO(0) + b_row * SA_STRIDE + b_q * 32;
        #pragma unroll
        for (int i = 0; i < 2; i++) {
            uint32_t h[4], l[4];
            cvt_split4(fB[i * 2 + 0], h[0], h[1], l[0], l[1]);
            cvt_split4(fB[i * 2 + 1], h[2], h[3], l[2], l[3]);
            *(uint4*)(bh + i * 16) = *(uint4*)h;
            *(uint4*)(bl + i * 16) = *(uint4*)l;
        }
    }
    __syncthreads();

    for (int kc = 0; kc < NCHUNK; kc++) {
        const int b = kc & 1;
        const bool has_next = (kc + 1 < NCHUNK);

        // issue global loads for next chunk (overlap with compute)
        if (has_next) {
            const float* ga = Abase + (kc + 1) * 64;
            const float* gw = Wbase + (kc + 1) * 64;
            #pragma unroll
            for (int i = 0; i < 8; i++) fA[i] = ((const float4*)ga)[i];
            #pragma unroll
            for (int i = 0; i < 4; i++) fB[i] = ((const float4*)gw)[i];
        }

        // ---- compute chunk kc from buffer b ----
        const uint32_t ahi_b = sb + OFF_AHI(b) + a_lds;
        const uint32_t alo_b = sb + OFF_ALO(b) + a_lds;
        const uint32_t bhi_b = sb + OFF_BHI(b) + b_lds;
        const uint32_t blo_b = sb + OFF_BLO(b) + b_lds;

        #pragma unroll
        for (int ks = 0; ks < 4; ks++) {
            const uint32_t kb = ks * 32;
            uint32_t ah[2][4], al[2][4], bh[2][4], bl[2][4];
            #pragma unroll
            for (int mi = 0; mi < 2; mi++) {
                LDSM_X4(ah[mi][0], ah[mi][1], ah[mi][2], ah[mi][3],
                        ahi_b + mi * 16 * SA_STRIDE + kb);
                LDSM_X4(al[mi][0], al[mi][1], al[mi][2], al[mi][3],
                        alo_b + mi * 16 * SA_STRIDE + kb);
            }
            #pragma unroll
            for (int nt = 0; nt < 2; nt++) {
                LDSM_X4(bh[nt][0], bh[nt][1], bh[nt][2], bh[nt][3],
                        bhi_b + nt * 16 * SA_STRIDE + kb);
                LDSM_X4(bl[nt][0], bl[nt][1], bl[nt][2], bl[nt][3],
                        blo_b + nt * 16 * SA_STRIDE + kb);
            }
            #pragma unroll
            for (int mi = 0; mi < 2; mi++) {
                #pragma unroll
                for (int nt = 0; nt < 2; nt++) {
                    // hi * hi
                    MMA16816(acc[mi][nt * 2 + 0], ah[mi][0], ah[mi][1], ah[mi][2], ah[mi][3],
                             bh[nt][0], bh[nt][1]);
                    MMA16816(acc[mi][nt * 2 + 1], ah[mi][0], ah[mi][1], ah[mi][2], ah[mi][3],
                             bh[nt][2], bh[nt][3]);
                    // hi * lo
                    MMA16816(acc[mi][nt * 2 + 0], ah[mi][0], ah[mi][1], ah[mi][2], ah[mi][3],
                             bl[nt][0], bl[nt][1]);
                    MMA16816(acc[mi][nt * 2 + 1], ah[mi][0], ah[mi][1], ah[mi][2], ah[mi][3],
                             bl[nt][2], bl[nt][3]);
                    // lo * hi
                    MMA16816(acc[mi][nt * 2 + 0], al[mi][0], al[mi][1], al[mi][2], al[mi][3],
                             bh[nt][0], bh[nt][1]);
                    MMA16816(acc[mi][nt * 2 + 1], al[mi][0], al[mi][1], al[mi][2], al[mi][3],
                             bh[nt][2], bh[nt][3]);
                }
            }
        }

        // ---- convert + store next chunk into buffer b^1 ----
        if (has_next) {
            const int nb = b ^ 1;
            char* ah = smem + OFF_AHI(nb) + a_row * SA_STRIDE + a_half * 64;
            char* al = smem + OFF_ALO(nb) + a_row * SA_STRIDE + a_half * 64;
            #pragma unroll
            for (int i = 0; i < 4; i++) {
                uint32_t h[4], l[4];
                cvt_split4(fA[i * 2 + 0], h[0], h[1], l[0], l[1]);
                cvt_split4(fA[i * 2 + 1], h[2], h[3], l[2], l[3]);
                *(uint4*)(ah + i * 16) = *(uint4*)h;
                *(uint4*)(al + i * 16) = *(uint4*)l;
            }
            char* bh = smem + OFF_BHI(nb) + b_row * SA_STRIDE + b_q * 32;
            char* bl = smem + OFF_BLO(nb) + b_row * SA_STRIDE + b_q * 32;
            #pragma unroll
            for (int i = 0; i < 2; i++) {
                uint32_t h[4], l[4];
                cvt_split4(fB[i * 2 + 0], h[0], h[1], l[0], l[1]);
                cvt_split4(fB[i * 2 + 1], h[2], h[3], l[2], l[3]);
                *(uint4*)(bh + i * 16) = *(uint4*)h;
                *(uint4*)(bl + i * 16) = *(uint4*)l;
            }
            __syncthreads();
        }
    }

    // ---- epilogue: C -> smem (stride 66 floats), then fused top-2 + stores ----
    __syncthreads();   // all warps done with last compute before reusing buffers
    float* Cs = (float*)smem;
    #pragma unroll
    for (int mi = 0; mi < 2; mi++) {
        #pragma unroll
        for (int ni = 0; ni < 4; ni++) {
            int r0 = wm * 32 + mi * 16 + (lane >> 2);
            int c  = wn * 32 + ni * 8 + (lane & 3) * 2;
            *(float2*)(Cs + r0 * CS + c)       = make_float2(acc[mi][ni][0], acc[mi][ni][1]);
            *(float2*)(Cs + (r0 + 8) * CS + c) = make_float2(acc[mi][ni][2], acc[mi][ni][3]);
        }
    }
    __syncthreads();

    // logits: each thread writes half a row (32 floats)
    {
        const int r = tid >> 1;
        const int cb = (tid & 1) * 32;
        float* lrow = logits + (size_t)(block_m + r) * N_EXP + cb;
        const float* src = Cs + r * CS + cb;
        #pragma unroll
        for (int i = 0; i < 8; i++) {
            float2 u = *(const float2*)(src + i * 4);
            float2 v = *(const float2*)(src + i * 4 + 2);
            *(float4*)(lrow + i * 4) = make_float4(u.x, u.y, v.x, v.y);
        }
    }

    // top-2 + renorm: threads 0..127, one row each
    if (tid < 128) {
        const float* row = Cs + tid * CS;
        float m1 = -3.4e38f, m2 = -3.4e38f;
        int i1 = 0, i2 = 0;
        #pragma unroll
        for (int e = 0; e < 64; e++) {
            float v = row[e];
            if (v > m1)      { m2 = m1; i2 = i1; m1 = v; i1 = e; }
            else if (v > m2) { m2 = v; i2 = e; }
        }
        const int t = block_m + tid;
        float w1 = 1.0f / (1.0f + expf(m2 - m1));
        wflat[t * 2 + 0] = w1;
        wflat[t * 2 + 1] = 1.0f - w1;
        g_idx[t]            = i1;
        g_idx[T_TOKENS + t] = i2;
    }
}

// ---------------------------------------------------------------------------
// Greedy capacity assignment: 1 block/expert, 1024-entry tiles (int4 + shfl scan)
// ---------------------------------------------------------------------------
__global__ __launch_bounds__(256)
void assign_kernel(const float* __restrict__ wflat,
                   float* __restrict__ out_idx,
                   float* __restrict__ out_w) {
    const int e = blockIdx.x;
    const int tid = threadIdx.x;
    const int lane = tid & 31, wid = tid >> 5;

    for (int i = tid; i < CAP; i += 256) {
        out_idx[e * CAP + i] = 0.0f;
        out_w[e * CAP + i]   = 0.0f;
    }
    __shared__ int wtot[8];
    __syncthreads();

    const int NT = (2 * T_TOKENS) / 1024;   // 32 tiles
    int running = 0;
    int4 v = ((const int4*)g_idx)[tid];

    for (int tile = 0; tile < NT; tile++) {
        int4 vn = make_int4(0, 0, 0, 0);
        if (tile + 1 < NT) vn = ((const int4*)g_idx)[(tile + 1) * 256 + tid];

        int m0 = (v.x == e), m1 = (v.y == e), m2 = (v.z == e), m3 = (v.w == e);
        int cnt = m0 + m1 + m2 + m3;
        int inc = cnt;
        #pragma unroll
        for (int off = 1; off < 32; off <<= 1) {
            int n = __shfl_up_sync(0xffffffffu, inc, off);
            if (lane >= off) inc += n;
        }
        if (lane == 31) wtot[wid] = inc;
        __syncthreads();
        int wexcl = 0, total = 0;
        #pragma unroll
        for (int w = 0; w < 8; w++) {
            int s = wtot[w];
            if (w < wid) wexcl += s;
            total += s;
        }
        int pos = running + wexcl + (inc - cnt);
        const int a0 = tile * 1024 + tid * 4;
        #pragma unroll
        for (int j = 0; j < 4; j++) {
            int m = (j == 0) ? m0 : (j == 1) ? m1 : (j == 2) ? m2 : m3;
            if (m) {
                if (pos < CAP) {
                    int a = a0 + j;
                    int token = a & (T_TOKENS - 1);
                    int slot  = a >> 14;
                    out_idx[e * CAP + pos] = (float)token;
                    out_w[e * CAP + pos]   = wflat[token * 2 + slot];
                }
                pos++;
            }
        }
        running += total;
        __syncthreads();
        v = vn;
    }
}

// ---------------------------------------------------------------------------
// Output layout (float32): [idx E*CAP | w E*CAP | wflat T*2 | logits T*E]
// ---------------------------------------------------------------------------
extern "C" void kernel_launch(void* const* d_in, const int* in_sizes, int n_in,
                              void* d_out, int out_size) {
    const float* hs;
    const float* wr;
    if (in_sizes[0] == N_EXP * H_DIM) {
        wr = (const float*)d_in[0];
        hs = (const float*)d_in[1];
    } else {
        hs = (const float*)d_in[0];
        wr = (const float*)d_in[1];
    }

    float* out     = (float*)d_out;
    float* out_idx = out;
    float* out_w   = out + N_EXP * CAP;
    float* wflat   = out + 2 * N_EXP * CAP;
    float* logits  = out + 2 * N_EXP * CAP + 2 * T_TOKENS;

    cudaFuncSetAttribute(gemm_topk_kernel, cudaFuncAttributeMaxDynamicSharedMemorySize,
                         SMEM_BYTES);
    gemm_topk_kernel<<<T_TOKENS / 128, 256, SMEM_BYTES>>>(hs, wr, logits, wflat);
    assign_kernel<<<N_EXP, 256>>>(wflat, out_idx, out_w);
}